// round 1
// baseline (speedup 1.0000x reference)
#include <cuda_runtime.h>
#include <math.h>

#define N_   8
#define C_   64
#define H_   256
#define W_   256
#define G_   8
#define K2_  9
#define GK2_ 72
#define ROWS 8

// scratch (no cudaMalloc allowed)
__device__ float g_pooled[N_ * C_];   // mean over HxW per (n,c)
__device__ float g_lf[N_ * GK2_];     // tanh(BN(pooled @ conv_w^T)) per (n, g*9+t)

// ---------------------------------------------------------------------------
// Kernel A: per-(n,c) plane mean. 512 blocks x 256 threads, float4 loads.
// ---------------------------------------------------------------------------
__global__ void pool_kernel(const float* __restrict__ x) {
    const int plane = blockIdx.x;                       // n*C + c
    const float4* xv = (const float4*)(x + (size_t)plane * H_ * W_);
    const int tid = threadIdx.x;
    float s = 0.f;
    #pragma unroll
    for (int i = 0; i < (H_ * W_ / 4) / 256; ++i) {     // 64 iterations
        float4 v = xv[tid + i * 256];
        s += (v.x + v.y) + (v.z + v.w);
    }
    #pragma unroll
    for (int o = 16; o; o >>= 1) s += __shfl_down_sync(0xffffffffu, s, o);
    __shared__ float ws[8];
    if ((tid & 31) == 0) ws[tid >> 5] = s;
    __syncthreads();
    if (tid < 8) {
        float t = ws[tid];
        #pragma unroll
        for (int o = 4; o; o >>= 1) t += __shfl_down_sync(0xffu, t, o);
        if (tid == 0) g_pooled[plane] = t * (1.f / (H_ * W_));
    }
}

// ---------------------------------------------------------------------------
// Kernel B: lf = tanh(BN(pooled @ conv_w^T)). 576 entries, dot over C=64.
// ---------------------------------------------------------------------------
__global__ void lf_kernel(const float* __restrict__ conv_w,
                          const float* __restrict__ bn_gamma,
                          const float* __restrict__ bn_beta,
                          const float* __restrict__ bn_mean,
                          const float* __restrict__ bn_var) {
    const int idx = blockIdx.x * blockDim.x + threadIdx.x;
    if (idx >= N_ * GK2_) return;
    const int n = idx / GK2_;
    const int j = idx % GK2_;
    const float* p = g_pooled + n * C_;
    const float* w = conv_w + j * C_;
    float acc = 0.f;
    #pragma unroll
    for (int c = 0; c < C_; ++c) acc = fmaf(p[c], w[c], acc);
    const float inv = rsqrtf(bn_var[j] + 1e-5f);
    const float v = (acc - bn_mean[j]) * (bn_gamma[j] * inv) + bn_beta[j];
    g_lf[idx] = tanhf(v);
}

// ---------------------------------------------------------------------------
// Kernel C: 3x3 reflect-pad dynamic-filter conv + DSA affine epilogue.
// grid = (H/ROWS, C, N), 256 threads. SMEM tile: (ROWS+2) x (W+2).
// ---------------------------------------------------------------------------
__global__ __launch_bounds__(256) void main_kernel(
        const float* __restrict__ x,
        const float* __restrict__ lamb_l,
        const float* __restrict__ lamb_h,
        const float* __restrict__ inside_all,
        float* __restrict__ out) {
    __shared__ float sm[ROWS + 2][W_ + 2];
    __shared__ float wlf[K2_];

    const int n  = blockIdx.z;
    const int c  = blockIdx.y;
    const int y0 = blockIdx.x * ROWS;
    const int tid = threadIdx.x;

    const size_t plane_off = (size_t)(n * C_ + c) * H_ * W_;
    const float* xp = x + plane_off;

    if (tid < K2_) wlf[tid] = g_lf[n * GK2_ + (c >> 3) * K2_ + tid];

    // cooperative tile load with reflect padding (pad=1, jnp "reflect": -1->1, H->H-2)
    for (int i = tid; i < (ROWS + 2) * (W_ + 2); i += 256) {
        int r  = i / (W_ + 2);
        int cc = i % (W_ + 2);
        int gr = y0 - 1 + r;
        gr = gr < 0 ? -gr : (gr >= H_ ? 2 * H_ - 2 - gr : gr);
        int gc = cc - 1;
        gc = gc < 0 ? -gc : (gc >= W_ ? 2 * W_ - 2 - gc : gc);
        sm[r][cc] = xp[gr * W_ + gc];
    }
    __syncthreads();

    const float ll  = lamb_l[c];
    const float lh1 = lamb_h[c] + 1.f;
    const float ia  = inside_all[c];
    const float ia1 = ia + 1.f;
    const float gap = g_pooled[n * C_ + c];
    const float bias = -ia * gap;   // (low*(ia+1) - ia*gap)*ll

    const float w0 = wlf[0], w1 = wlf[1], w2 = wlf[2];
    const float w3 = wlf[3], w4 = wlf[4], w5 = wlf[5];
    const float w6 = wlf[6], w7 = wlf[7], w8 = wlf[8];

    const int w = tid;  // output column
    float* op = out + plane_off + (size_t)y0 * W_ + w;

    #pragma unroll
    for (int ry = 0; ry < ROWS; ++ry) {
        float acc;
        acc = w0 * sm[ry    ][w    ];
        acc = fmaf(w1, sm[ry    ][w + 1], acc);
        acc = fmaf(w2, sm[ry    ][w + 2], acc);
        acc = fmaf(w3, sm[ry + 1][w    ], acc);
        acc = fmaf(w4, sm[ry + 1][w + 1], acc);
        acc = fmaf(w5, sm[ry + 1][w + 2], acc);
        acc = fmaf(w6, sm[ry + 2][w    ], acc);
        acc = fmaf(w7, sm[ry + 2][w + 1], acc);
        acc = fmaf(w8, sm[ry + 2][w + 2], acc);
        const float xv = sm[ry + 1][w + 1];
        op[ry * W_] = fmaf(acc, ia1, bias) * ll + xv * lh1;
    }
}

// ---------------------------------------------------------------------------
extern "C" void kernel_launch(void* const* d_in, const int* in_sizes, int n_in,
                              void* d_out, int out_size) {
    const float* x          = (const float*)d_in[0];
    const float* conv_w     = (const float*)d_in[1];
    const float* bn_gamma   = (const float*)d_in[2];
    const float* bn_beta    = (const float*)d_in[3];
    const float* bn_mean    = (const float*)d_in[4];
    const float* bn_var     = (const float*)d_in[5];
    const float* lamb_l     = (const float*)d_in[6];
    const float* lamb_h     = (const float*)d_in[7];
    const float* inside_all = (const float*)d_in[8];
    float* out = (float*)d_out;

    pool_kernel<<<N_ * C_, 256>>>(x);
    lf_kernel<<<(N_ * GK2_ + 255) / 256, 256>>>(conv_w, bn_gamma, bn_beta, bn_mean, bn_var);
    dim3 grid(H_ / ROWS, C_, N_);
    main_kernel<<<grid, 256>>>(x, lamb_l, lamb_h, inside_all, out);
}

// round 2
// speedup vs baseline: 1.8447x; 1.8447x over previous
#include <cuda_runtime.h>
#include <math.h>

#define N_   8
#define C_   64
#define H_   256
#define W_   256
#define K2_  9
#define GK2_ 72
#define TROWS 32                 // output rows per tile
#define SROWS (TROWS + 2)        // 34 smem rows
#define SPITCH 264               // smem row pitch (floats); 264*4 % 16 == 0

// scratch (no cudaMalloc allowed)
__device__ float g_part[N_ * C_ * 4];   // quarter-plane partial sums
__device__ float g_pooled[N_ * C_];     // plane means
__device__ float g_lf[N_ * GK2_];       // tanh(BN(pooled @ conv_w^T))

// ---------------------------------------------------------------------------
// Kernel A: quarter-plane partial sums. 2048 blocks x 256 threads.
// ---------------------------------------------------------------------------
__global__ __launch_bounds__(256) void pool_part_kernel(const float* __restrict__ x) {
    const int b = blockIdx.x;                 // plane*4 + quarter
    const float4* xv = (const float4*)(x + (size_t)b * (H_ * W_ / 4));
    const int tid = threadIdx.x;
    float s = 0.f;
    #pragma unroll
    for (int i = 0; i < 16; ++i) {            // 16 * 256 * 4 = 16384 floats
        float4 v = xv[tid + i * 256];
        s += (v.x + v.y) + (v.z + v.w);
    }
    #pragma unroll
    for (int o = 16; o; o >>= 1) s += __shfl_down_sync(0xffffffffu, s, o);
    __shared__ float ws[8];
    if ((tid & 31) == 0) ws[tid >> 5] = s;
    __syncthreads();
    if (tid < 8) {
        float t = ws[tid];
        #pragma unroll
        for (int o = 4; o; o >>= 1) t += __shfl_down_sync(0xffu, t, o);
        if (tid == 0) g_part[b] = t;
    }
}

// ---------------------------------------------------------------------------
// Kernel B: finalize pooled means + lf = tanh(BN(pooled @ conv_w^T)).
// grid = N_, 128 threads.
// ---------------------------------------------------------------------------
__global__ __launch_bounds__(128) void lf_kernel(
        const float* __restrict__ conv_w,
        const float* __restrict__ bn_gamma,
        const float* __restrict__ bn_beta,
        const float* __restrict__ bn_mean,
        const float* __restrict__ bn_var) {
    const int n = blockIdx.x;
    const int tid = threadIdx.x;
    __shared__ float ps[C_];
    if (tid < C_) {
        const float* p = g_part + (n * C_ + tid) * 4;
        float m = (p[0] + p[1] + p[2] + p[3]) * (1.f / (H_ * W_));
        ps[tid] = m;
        g_pooled[n * C_ + tid] = m;
    }
    __syncthreads();
    if (tid < GK2_) {
        const float* w = conv_w + tid * C_;
        float acc = 0.f;
        #pragma unroll
        for (int c = 0; c < C_; ++c) acc = fmaf(ps[c], w[c], acc);
        const float inv = rsqrtf(bn_var[tid] + 1e-5f);
        const float v = (acc - bn_mean[tid]) * (bn_gamma[tid] * inv) + bn_beta[tid];
        g_lf[n * GK2_ + tid] = tanhf(v);
    }
}

// ---------------------------------------------------------------------------
// Kernel C: 3x3 reflect-pad dynamic-filter conv + DSA affine.
// grid = (H/TROWS, C, N), 256 threads. Each thread: 4 cols x 8 rows,
// rolling 3-row register tap windows (3 LDS per new row instead of 9/output).
// ---------------------------------------------------------------------------
__global__ __launch_bounds__(256) void main_kernel(
        const float* __restrict__ x,
        const float* __restrict__ lamb_l,
        const float* __restrict__ lamb_h,
        const float* __restrict__ inside_all,
        float* __restrict__ out) {
    __shared__ float sm[SROWS][SPITCH];
    __shared__ float wlf[K2_];

    const int n   = blockIdx.z;
    const int c   = blockIdx.y;
    const int y0  = blockIdx.x * TROWS;
    const int tid = threadIdx.x;

    const size_t plane_off = (size_t)(n * C_ + c) * H_ * W_;
    const float* xp = x + plane_off;

    if (tid < K2_) wlf[tid] = g_lf[n * GK2_ + (c >> 3) * K2_ + tid];

    // ---- tile load: interior via float4, halos via 2 scalars/row -----------
    // smem abs cols: [3] = left halo (gc=-1), [4..259] = gc 0..255, [260] = right halo
    #pragma unroll
    for (int it = 0; it < (SROWS * 64 + 255) / 256; ++it) {
        int i = tid + it * 256;
        if (i < SROWS * 64) {
            int r = i >> 6;
            int j = i & 63;
            int gr = y0 - 1 + r;
            gr = gr < 0 ? 1 : (gr >= H_ ? 2 * H_ - 2 - gr : gr);
            float4 v = ((const float4*)(xp + gr * W_))[j];
            *(float4*)&sm[r][4 + 4 * j] = v;
        }
    }
    if (tid < 2 * SROWS) {
        int r = tid >> 1;
        int side = tid & 1;
        int gr = y0 - 1 + r;
        gr = gr < 0 ? 1 : (gr >= H_ ? 2 * H_ - 2 - gr : gr);
        if (side == 0) sm[r][3]   = xp[gr * W_ + 1];        // reflect of col -1
        else           sm[r][260] = xp[gr * W_ + W_ - 2];   // reflect of col 256
    }
    __syncthreads();

    // ---- per-channel constants ---------------------------------------------
    const float ll  = lamb_l[c];
    const float lh1 = lamb_h[c] + 1.f;
    const float ia  = inside_all[c];
    const float A   = (ia + 1.f) * ll;
    const float Bc  = -ia * g_pooled[n * C_ + c] * ll;

    const float w0 = wlf[0], w1 = wlf[1], w2 = wlf[2];
    const float w3 = wlf[3], w4 = wlf[4], w5 = wlf[5];
    const float w6 = wlf[6], w7 = wlf[7], w8 = wlf[8];

    // ---- compute: thread (q, rs) -> cols 4q..4q+3, rows rs*8..rs*8+7 -------
    const int q    = tid & 63;
    const int rs   = tid >> 6;
    const int base = 4 * q;          // output col base; tap abs cols 3+base..8+base
    const int yb   = rs * 8;         // first tap row in smem coords

    float rows[3][6];
    #define LOADROW(R, D) do {                                       \
        float2 _a = *(const float2*)&sm[(R)][2 + base];              \
        float4 _b = *(const float4*)&sm[(R)][4 + base];              \
        float2 _c = *(const float2*)&sm[(R)][8 + base];              \
        (D)[0] = _a.y; (D)[1] = _b.x; (D)[2] = _b.y;                 \
        (D)[3] = _b.z; (D)[4] = _b.w; (D)[5] = _c.x;                 \
    } while (0)

    LOADROW(yb + 0, rows[0]);
    LOADROW(yb + 1, rows[1]);

    float4* op = (float4*)(out + plane_off + (size_t)(y0 + yb) * W_ + base);

    #pragma unroll
    for (int k = 0; k < 8; ++k) {
        LOADROW(yb + 2 + k, rows[(k + 2) % 3]);
        const float* t0 = rows[k % 3];
        const float* t1 = rows[(k + 1) % 3];
        const float* t2 = rows[(k + 2) % 3];
        float4 o;
        #pragma unroll
        for (int j = 0; j < 4; ++j) {
            float acc;
            acc = w0 * t0[j];
            acc = fmaf(w1, t0[j + 1], acc);
            acc = fmaf(w2, t0[j + 2], acc);
            acc = fmaf(w3, t1[j],     acc);
            acc = fmaf(w4, t1[j + 1], acc);
            acc = fmaf(w5, t1[j + 2], acc);
            acc = fmaf(w6, t2[j],     acc);
            acc = fmaf(w7, t2[j + 1], acc);
            acc = fmaf(w8, t2[j + 2], acc);
            float r = fmaf(acc, A, fmaf(t1[j + 1], lh1, Bc));
            ((float*)&o)[j] = r;
        }
        op[k * (W_ / 4)] = o;
    }
    #undef LOADROW
}

// ---------------------------------------------------------------------------
extern "C" void kernel_launch(void* const* d_in, const int* in_sizes, int n_in,
                              void* d_out, int out_size) {
    const float* x          = (const float*)d_in[0];
    const float* conv_w     = (const float*)d_in[1];
    const float* bn_gamma   = (const float*)d_in[2];
    const float* bn_beta    = (const float*)d_in[3];
    const float* bn_mean    = (const float*)d_in[4];
    const float* bn_var     = (const float*)d_in[5];
    const float* lamb_l     = (const float*)d_in[6];
    const float* lamb_h     = (const float*)d_in[7];
    const float* inside_all = (const float*)d_in[8];
    float* out = (float*)d_out;

    pool_part_kernel<<<N_ * C_ * 4, 256>>>(x);
    lf_kernel<<<N_, 128>>>(conv_w, bn_gamma, bn_beta, bn_mean, bn_var);
    dim3 grid(H_ / TROWS, C_, N_);
    main_kernel<<<grid, 256>>>(x, lamb_l, lamb_h, inside_all, out);
}

// round 3
// speedup vs baseline: 1.9314x; 1.0470x over previous
#include <cuda_runtime.h>
#include <math.h>

#define N_   8
#define C_   64
#define H_   256
#define W_   256
#define K2_  9
#define GK2_ 72

// scratch (no cudaMalloc allowed)
__device__ float g_part[N_ * C_ * 4];   // quarter-plane partial sums
__device__ float g_pooled[N_ * C_];     // plane means
__device__ float g_lf[N_ * GK2_];       // tanh(BN(pooled @ conv_w^T))

// ---------------------------------------------------------------------------
// Kernel A: quarter-plane partial sums. 2048 blocks x 256 threads.
// ---------------------------------------------------------------------------
__global__ __launch_bounds__(256) void pool_part_kernel(const float* __restrict__ x) {
    const int b = blockIdx.x;                 // plane*4 + quarter
    const float4* xv = (const float4*)(x + (size_t)b * (H_ * W_ / 4));
    const int tid = threadIdx.x;
    float s = 0.f;
    #pragma unroll
    for (int i = 0; i < 16; ++i) {
        float4 v = xv[tid + i * 256];
        s += (v.x + v.y) + (v.z + v.w);
    }
    #pragma unroll
    for (int o = 16; o; o >>= 1) s += __shfl_down_sync(0xffffffffu, s, o);
    __shared__ float ws[8];
    if ((tid & 31) == 0) ws[tid >> 5] = s;
    __syncthreads();
    if (tid < 8) {
        float t = ws[tid];
        #pragma unroll
        for (int o = 4; o; o >>= 1) t += __shfl_down_sync(0xffu, t, o);
        if (tid == 0) g_part[b] = t;
    }
}

// ---------------------------------------------------------------------------
// Kernel B: finalize pooled means + lf = tanh(BN(pooled @ conv_w^T)).
// ---------------------------------------------------------------------------
__global__ __launch_bounds__(128) void lf_kernel(
        const float* __restrict__ conv_w,
        const float* __restrict__ bn_gamma,
        const float* __restrict__ bn_beta,
        const float* __restrict__ bn_mean,
        const float* __restrict__ bn_var) {
    const int n = blockIdx.x;
    const int tid = threadIdx.x;
    __shared__ float ps[C_];
    if (tid < C_) {
        const float* p = g_part + (n * C_ + tid) * 4;
        float m = (p[0] + p[1] + p[2] + p[3]) * (1.f / (H_ * W_));
        ps[tid] = m;
        g_pooled[n * C_ + tid] = m;
    }
    __syncthreads();
    if (tid < GK2_) {
        const float* w = conv_w + tid * C_;
        float acc = 0.f;
        #pragma unroll
        for (int c = 0; c < C_; ++c) acc = fmaf(ps[c], w[c], acc);
        const float inv = rsqrtf(bn_var[tid] + 1e-5f);
        const float v = (acc - bn_mean[tid]) * (bn_gamma[tid] * inv) + bn_beta[tid];
        g_lf[n * GK2_ + tid] = tanhf(v);
    }
}

// ---------------------------------------------------------------------------
// Kernel C: smem-free 3x3 reflect stencil. One warp = one 4-row band of a
// full 256-wide row; 8 cols/thread; horizontal neighbors via SHFL (reflect
// edges resolve inside edge lanes); vertical via rolling 3x10 reg window.
// grid = (H/32, C, N), 256 threads (8 warps = 32 rows/block).
// ---------------------------------------------------------------------------
__global__ __launch_bounds__(256) void main_kernel(
        const float* __restrict__ x,
        const float* __restrict__ lamb_l,
        const float* __restrict__ lamb_h,
        const float* __restrict__ inside_all,
        float* __restrict__ out) {
    const int n    = blockIdx.z;
    const int c    = blockIdx.y;
    const int warp = threadIdx.x >> 5;
    const int lane = threadIdx.x & 31;
    const int yr0  = blockIdx.x * 32 + warp * 4;   // first output row of this warp

    const size_t plane_off = (size_t)(n * C_ + c) * H_ * W_;
    const float* xp = x + plane_off;

    // per-(n,g) dynamic 3x3 weights (broadcast loads)
    const float* lfp = g_lf + n * GK2_ + (c >> 3) * K2_;
    const float w0 = __ldg(lfp + 0), w1 = __ldg(lfp + 1), w2 = __ldg(lfp + 2);
    const float w3 = __ldg(lfp + 3), w4 = __ldg(lfp + 4), w5 = __ldg(lfp + 5);
    const float w6 = __ldg(lfp + 6), w7 = __ldg(lfp + 7), w8 = __ldg(lfp + 8);

    const float ll  = __ldg(lamb_l + c);
    const float lh1 = __ldg(lamb_h + c) + 1.f;
    const float ia  = __ldg(inside_all + c);
    const float A   = (ia + 1.f) * ll;
    const float Bc  = -ia * g_pooled[n * C_ + c] * ll;

    // window cols: 8*lane-1 .. 8*lane+8  (10 floats)
    float win[3][10];
    #define LOADROW(GR, D) do {                                            \
        int _g = (GR);                                                     \
        _g = _g < 0 ? -_g : (_g >= H_ ? 2 * H_ - 2 - _g : _g);             \
        const float4* _p = (const float4*)(xp + (size_t)_g * W_);          \
        float4 _L = __ldg(&_p[2 * lane]);                                  \
        float4 _R = __ldg(&_p[2 * lane + 1]);                              \
        float _lf = __shfl_up_sync(0xffffffffu, _R.w, 1);                  \
        float _rt = __shfl_down_sync(0xffffffffu, _L.x, 1);                \
        if (lane == 0)  _lf = _L.y;   /* reflect col -1 -> col 1   */      \
        if (lane == 31) _rt = _R.z;   /* reflect col 256 -> col 254 */     \
        (D)[0] = _lf;                                                      \
        (D)[1] = _L.x; (D)[2] = _L.y; (D)[3] = _L.z; (D)[4] = _L.w;        \
        (D)[5] = _R.x; (D)[6] = _R.y; (D)[7] = _R.z; (D)[8] = _R.w;        \
        (D)[9] = _rt;                                                      \
    } while (0)

    LOADROW(yr0 - 1, win[0]);
    LOADROW(yr0,     win[1]);

    float* ob = out + plane_off + (size_t)yr0 * W_ + 8 * lane;

    #pragma unroll
    for (int k = 0; k < 4; ++k) {
        LOADROW(yr0 + 1 + k, win[(k + 2) % 3]);
        const float* t0 = win[k % 3];
        const float* t1 = win[(k + 1) % 3];
        const float* t2 = win[(k + 2) % 3];
        float o[8];
        #pragma unroll
        for (int j = 0; j < 8; ++j) {
            float acc;
            acc = w0 * t0[j];
            acc = fmaf(w1, t0[j + 1], acc);
            acc = fmaf(w2, t0[j + 2], acc);
            acc = fmaf(w3, t1[j],     acc);
            acc = fmaf(w4, t1[j + 1], acc);
            acc = fmaf(w5, t1[j + 2], acc);
            acc = fmaf(w6, t2[j],     acc);
            acc = fmaf(w7, t2[j + 1], acc);
            acc = fmaf(w8, t2[j + 2], acc);
            o[j] = fmaf(acc, A, fmaf(t1[j + 1], lh1, Bc));
        }
        float4* op = (float4*)(ob + (size_t)k * W_);
        __stcs(op,     make_float4(o[0], o[1], o[2], o[3]));
        __stcs(op + 1, make_float4(o[4], o[5], o[6], o[7]));
    }
    #undef LOADROW
}

// ---------------------------------------------------------------------------
extern "C" void kernel_launch(void* const* d_in, const int* in_sizes, int n_in,
                              void* d_out, int out_size) {
    const float* x          = (const float*)d_in[0];
    const float* conv_w     = (const float*)d_in[1];
    const float* bn_gamma   = (const float*)d_in[2];
    const float* bn_beta    = (const float*)d_in[3];
    const float* bn_mean    = (const float*)d_in[4];
    const float* bn_var     = (const float*)d_in[5];
    const float* lamb_l     = (const float*)d_in[6];
    const float* lamb_h     = (const float*)d_in[7];
    const float* inside_all = (const float*)d_in[8];
    float* out = (float*)d_out;

    pool_part_kernel<<<N_ * C_ * 4, 256>>>(x);
    lf_kernel<<<N_, 128>>>(conv_w, bn_gamma, bn_beta, bn_mean, bn_var);
    dim3 grid(H_ / 32, C_, N_);
    main_kernel<<<grid, 256>>>(x, lamb_l, lamb_h, inside_all, out);
}

// round 4
// speedup vs baseline: 2.1278x; 1.1017x over previous
#include <cuda_runtime.h>
#include <math.h>

#define N_   8
#define C_   64
#define H_   256
#define W_   256
#define K2_  9
#define GK2_ 72
#define RPW  8                    // output rows per warp

// scratch (no cudaMalloc allowed)
__device__ float g_part[N_ * C_ * 4];   // quarter-plane partial sums
__device__ float g_pooled[N_ * C_];     // plane means
__device__ float g_lf[N_ * GK2_];       // tanh(BN(pooled @ conv_w^T))

// ---------------------------------------------------------------------------
// Kernel A: quarter-plane partial sums. 2048 blocks x 256 threads.
// Reads x FORWARD (increasing address).
// ---------------------------------------------------------------------------
__global__ __launch_bounds__(256) void pool_part_kernel(const float* __restrict__ x) {
    const int b = blockIdx.x;                 // plane*4 + quarter
    const float4* xv = (const float4*)(x + (size_t)b * (H_ * W_ / 4));
    const int tid = threadIdx.x;
    float s = 0.f;
    #pragma unroll
    for (int i = 0; i < 16; ++i) {
        float4 v = xv[tid + i * 256];
        s += (v.x + v.y) + (v.z + v.w);
    }
    #pragma unroll
    for (int o = 16; o; o >>= 1) s += __shfl_down_sync(0xffffffffu, s, o);
    __shared__ float ws[8];
    if ((tid & 31) == 0) ws[tid >> 5] = s;
    __syncthreads();
    if (tid < 8) {
        float t = ws[tid];
        #pragma unroll
        for (int o = 4; o; o >>= 1) t += __shfl_down_sync(0xffu, t, o);
        if (tid == 0) g_part[b] = t;
    }
}

// ---------------------------------------------------------------------------
// Kernel B: finalize pooled means + lf = tanh(BN(pooled @ conv_w^T)).
// ---------------------------------------------------------------------------
__global__ __launch_bounds__(128) void lf_kernel(
        const float* __restrict__ conv_w,
        const float* __restrict__ bn_gamma,
        const float* __restrict__ bn_beta,
        const float* __restrict__ bn_mean,
        const float* __restrict__ bn_var) {
    const int n = blockIdx.x;
    const int tid = threadIdx.x;
    __shared__ float ps[C_];
    if (tid < C_) {
        const float* p = g_part + (n * C_ + tid) * 4;
        float m = (p[0] + p[1] + p[2] + p[3]) * (1.f / (H_ * W_));
        ps[tid] = m;
        g_pooled[n * C_ + tid] = m;
    }
    __syncthreads();
    if (tid < GK2_) {
        const float* w = conv_w + tid * C_;
        float acc = 0.f;
        #pragma unroll
        for (int c = 0; c < C_; ++c) acc = fmaf(ps[c], w[c], acc);
        const float inv = rsqrtf(bn_var[tid] + 1e-5f);
        const float v = (acc - bn_mean[tid]) * (bn_gamma[tid] * inv) + bn_beta[tid];
        g_lf[n * GK2_ + tid] = tanhf(v);
    }
}

// ---------------------------------------------------------------------------
// Kernel C: smem-free 3x3 reflect stencil, REVERSE traversal for L2 reuse.
// One warp = RPW-row band of a full 256-wide row; 8 cols/thread; horizontal
// neighbors via SHFL; vertical via rolling 3x10 reg window.
// grid = (H/(8*RPW), C, N), 256 threads (8 warps).
// ---------------------------------------------------------------------------
__global__ __launch_bounds__(256) void main_kernel(
        const float* __restrict__ x,
        const float* __restrict__ lamb_l,
        const float* __restrict__ lamb_h,
        const float* __restrict__ inside_all,
        float* __restrict__ out) {
    // reversed mapping: first-scheduled blocks touch the highest addresses,
    // which the (forward-reading) pool pass left resident in L2.
    const int n    = (N_ - 1) - blockIdx.z;
    const int c    = (C_ - 1) - blockIdx.y;
    const int tile = (gridDim.x - 1) - blockIdx.x;
    const int warp = 7 - (threadIdx.x >> 5);
    const int lane = threadIdx.x & 31;
    const int yr0  = tile * (8 * RPW) + warp * RPW;   // first output row

    const size_t plane_off = (size_t)(n * C_ + c) * H_ * W_;
    const float* xp = x + plane_off;

    const float* lfp = g_lf + n * GK2_ + (c >> 3) * K2_;
    const float w0 = __ldg(lfp + 0), w1 = __ldg(lfp + 1), w2 = __ldg(lfp + 2);
    const float w3 = __ldg(lfp + 3), w4 = __ldg(lfp + 4), w5 = __ldg(lfp + 5);
    const float w6 = __ldg(lfp + 6), w7 = __ldg(lfp + 7), w8 = __ldg(lfp + 8);

    const float ll  = __ldg(lamb_l + c);
    const float lh1 = __ldg(lamb_h + c) + 1.f;
    const float ia  = __ldg(inside_all + c);
    const float A   = (ia + 1.f) * ll;
    const float Bc  = -ia * g_pooled[n * C_ + c] * ll;

    // window cols: 8*lane-1 .. 8*lane+8  (10 floats)
    float win[3][10];
    #define LOADROW(GR, D) do {                                            \
        int _g = (GR);                                                     \
        _g = _g < 0 ? -_g : (_g >= H_ ? 2 * H_ - 2 - _g : _g);             \
        const float4* _p = (const float4*)(xp + (size_t)_g * W_);          \
        float4 _L = __ldg(&_p[2 * lane]);                                  \
        float4 _R = __ldg(&_p[2 * lane + 1]);                              \
        float _lf = __shfl_up_sync(0xffffffffu, _R.w, 1);                  \
        float _rt = __shfl_down_sync(0xffffffffu, _L.x, 1);                \
        if (lane == 0)  _lf = _L.y;   /* reflect col -1 -> col 1   */      \
        if (lane == 31) _rt = _R.z;   /* reflect col 256 -> col 254 */     \
        (D)[0] = _lf;                                                      \
        (D)[1] = _L.x; (D)[2] = _L.y; (D)[3] = _L.z; (D)[4] = _L.w;        \
        (D)[5] = _R.x; (D)[6] = _R.y; (D)[7] = _R.z; (D)[8] = _R.w;        \
        (D)[9] = _rt;                                                      \
    } while (0)

    LOADROW(yr0 - 1, win[0]);
    LOADROW(yr0,     win[1]);

    float* ob = out + plane_off + (size_t)yr0 * W_ + 8 * lane;

    #pragma unroll
    for (int k = 0; k < RPW; ++k) {
        LOADROW(yr0 + 1 + k, win[(k + 2) % 3]);
        const float* t0 = win[k % 3];
        const float* t1 = win[(k + 1) % 3];
        const float* t2 = win[(k + 2) % 3];
        float o[8];
        #pragma unroll
        for (int j = 0; j < 8; ++j) {
            float acc;
            acc = w0 * t0[j];
            acc = fmaf(w1, t0[j + 1], acc);
            acc = fmaf(w2, t0[j + 2], acc);
            acc = fmaf(w3, t1[j],     acc);
            acc = fmaf(w4, t1[j + 1], acc);
            acc = fmaf(w5, t1[j + 2], acc);
            acc = fmaf(w6, t2[j],     acc);
            acc = fmaf(w7, t2[j + 1], acc);
            acc = fmaf(w8, t2[j + 2], acc);
            o[j] = fmaf(acc, A, fmaf(t1[j + 1], lh1, Bc));
        }
        float4* op = (float4*)(ob + (size_t)k * W_);
        __stcs(op,     make_float4(o[0], o[1], o[2], o[3]));
        __stcs(op + 1, make_float4(o[4], o[5], o[6], o[7]));
    }
    #undef LOADROW
}

// ---------------------------------------------------------------------------
extern "C" void kernel_launch(void* const* d_in, const int* in_sizes, int n_in,
                              void* d_out, int out_size) {
    const float* x          = (const float*)d_in[0];
    const float* conv_w     = (const float*)d_in[1];
    const float* bn_gamma   = (const float*)d_in[2];
    const float* bn_beta    = (const float*)d_in[3];
    const float* bn_mean    = (const float*)d_in[4];
    const float* bn_var     = (const float*)d_in[5];
    const float* lamb_l     = (const float*)d_in[6];
    const float* lamb_h     = (const float*)d_in[7];
    const float* inside_all = (const float*)d_in[8];
    float* out = (float*)d_out;

    pool_part_kernel<<<N_ * C_ * 4, 256>>>(x);
    lf_kernel<<<N_, 128>>>(conv_w, bn_gamma, bn_beta, bn_mean, bn_var);
    dim3 grid(H_ / (8 * RPW), C_, N_);
    main_kernel<<<grid, 256>>>(x, lamb_l, lamb_h, inside_all, out);
}